// round 16
// baseline (speedup 1.0000x reference)
#include <cuda_runtime.h>
#include <cuda_fp16.h>
#include <math.h>
#include <stdint.h>

#define N_NODES 50000
#define N_EDGES 625000
#define DIM 128
#define N_LAYERS 3
#define N_GRAPHS 64
#define LN_EPS 1e-5f

__device__ __forceinline__ uint32_t smem_to_u32(const void* smem_ptr) {
    uint32_t addr;
    asm("{ .reg .u64 tmp; cvta.to.shared.u64 tmp, %1; cvt.u32.u64 %0, tmp; }"
        : "=r"(addr) : "l"(smem_ptr));
    return addr;
}

// ---- warp MMA primitives (baseline PTX, sm_80+) ----
#define LDSM_X4(r, addr) \
    asm volatile("ldmatrix.sync.aligned.m8n8.x4.shared.b16 {%0,%1,%2,%3}, [%4];" \
        : "=r"((r)[0]), "=r"((r)[1]), "=r"((r)[2]), "=r"((r)[3]) : "r"(addr))
#define LDSM_X2(r, addr) \
    asm volatile("ldmatrix.sync.aligned.m8n8.x2.shared.b16 {%0,%1}, [%2];" \
        : "=r"((r)[0]), "=r"((r)[1]) : "r"(addr))
#define MMA16816F16(d, a, b) \
    asm volatile("mma.sync.aligned.m16n8k16.row.col.f32.f16.f16.f32 " \
        "{%0,%1,%2,%3}, {%4,%5,%6,%7}, {%8,%9}, {%0,%1,%2,%3};" \
        : "+f"((d)[0]), "+f"((d)[1]), "+f"((d)[2]), "+f"((d)[3]) \
        : "r"((a)[0]), "r"((a)[1]), "r"((a)[2]), "r"((a)[3]), \
          "r"((b)[0]), "r"((b)[1]))
#define CP_ASYNC16(dst, src) \
    asm volatile("cp.async.ca.shared.global [%0], [%1], 16;" \
        :: "r"(dst), "l"(src) : "memory")
#define CP_ASYNC_COMMIT() asm volatile("cp.async.commit_group;" ::: "memory")
#define CP_ASYNC_WAIT0()  asm volatile("cp.async.wait_group 0;" ::: "memory")

// ================= device scratch =================
__device__ float g_h[N_NODES * DIM];
__device__ __half g_h16[N_NODES * DIM];    // fp16 mirror of h for agg gather
__device__ __half g_aF16[N_NODES * DIM];   // fp16 aggregates
__device__ __half g_aB16[N_NODES * DIM];
__device__ float g_scores[N_NODES];
__device__ float g_M[9 * DIM * DIM];
__device__ float g_bc[N_LAYERS * DIM];
__device__ __half g_Wh[10 * DIM * DIM];
__device__ int g_is64;
// CSR
__device__ int g_deg[N_NODES];
__device__ int g_off[N_NODES + 1];
__device__ int g_cur[N_NODES];
__device__ int g_srcS[N_EDGES];
__device__ int g_bsum[256];

#define SCAN_BLOCKS ((N_NODES + 255) / 256)

// ================= dtype detection =================
__global__ void detect_kernel(const unsigned int* __restrict__ p)
{
    __shared__ int nz;
    if (threadIdx.x == 0) nz = 0;
    __syncthreads();
    for (int i = threadIdx.x; i < 4096; i += blockDim.x)
        if (p[2 * i + 1] != 0u) atomicOr(&nz, 1);
    __syncthreads();
    if (threadIdx.x == 0) g_is64 = nz ? 0 : 1;
}

__device__ __forceinline__ int load_idx(const void* buf, long long i)
{
    int v;
    if (g_is64) v = (int)((const long long*)buf)[i];
    else        v = ((const int*)buf)[i];
    v = v < 0 ? 0 : (v >= N_NODES ? N_NODES - 1 : v);
    return v;
}

// ================= CSR build =================
__global__ void zero_int_kernel(int* __restrict__ p, int n)
{
    int i = blockIdx.x * blockDim.x + threadIdx.x;
    if (i < n) p[i] = 0;
}

__global__ void count_kernel(const void* __restrict__ ei, int* __restrict__ deg)
{
    int e = blockIdx.x * blockDim.x + threadIdx.x;
    if (e >= N_EDGES) return;
    int d = load_idx(ei, (long long)N_EDGES + e);
    atomicAdd(&deg[d], 1);
}

__global__ void scan_local_kernel(const int* __restrict__ deg,
                                  int* __restrict__ off,
                                  int* __restrict__ bsum)
{
    __shared__ int tmp[256];
    int t = threadIdx.x;
    int node = blockIdx.x * 256 + t;
    int v = (node < N_NODES) ? deg[node] : 0;
    tmp[t] = v;
    __syncthreads();
    #pragma unroll
    for (int o = 1; o < 256; o <<= 1) {
        int u = (t >= o) ? tmp[t - o] : 0;
        __syncthreads();
        tmp[t] += u;
        __syncthreads();
    }
    if (node < N_NODES) off[node] = tmp[t] - v;
    if (t == 255) bsum[blockIdx.x] = tmp[255];
}

__global__ void scan_bsum_kernel(int* __restrict__ bsum, int* __restrict__ off)
{
    __shared__ int tmp[256];
    int t = threadIdx.x;
    int v = (t < SCAN_BLOCKS) ? bsum[t] : 0;
    tmp[t] = v;
    __syncthreads();
    #pragma unroll
    for (int o = 1; o < 256; o <<= 1) {
        int u = (t >= o) ? tmp[t - o] : 0;
        __syncthreads();
        tmp[t] += u;
        __syncthreads();
    }
    if (t < SCAN_BLOCKS) bsum[t] = tmp[t] - v;
    if (t == 255) off[N_NODES] = tmp[255];
}

__global__ void scan_add_kernel(int* __restrict__ off,
                                const int* __restrict__ bsum,
                                int* __restrict__ cur)
{
    int node = blockIdx.x * 256 + threadIdx.x;
    if (node >= N_NODES) return;
    int o = off[node] + bsum[blockIdx.x];
    off[node] = o;
    cur[node] = o;
}

__global__ void scatter_kernel(const void* __restrict__ ei,
                               int* __restrict__ cur,
                               int* __restrict__ srcS)
{
    int e = blockIdx.x * blockDim.x + threadIdx.x;
    if (e >= N_EDGES) return;
    int s = load_idx(ei, e);
    int d = load_idx(ei, (long long)N_EDGES + e);
    int pos = atomicAdd(&cur[d], 1);
    srcS[pos] = s;
}

// ================= aggregation (warp per dst node, 8-wide, fp16 in+out) ========
__global__ void agg_kernel(const int* __restrict__ off,
                           const int* __restrict__ srcS,
                           const float* __restrict__ scores,
                           const __half* __restrict__ h16,
                           uint2* __restrict__ aF16,
                           uint2* __restrict__ aB16)
{
    int node = (blockIdx.x * blockDim.x + threadIdx.x) >> 5;
    int lane = threadIdx.x & 31;
    if (node >= N_NODES) return;
    int lo = off[node], hi = off[node + 1];
    float sd = scores[node];
    const uint2* h2 = reinterpret_cast<const uint2*>(h16);
    float4 af = make_float4(0.f, 0.f, 0.f, 0.f);
    float4 ab = make_float4(0.f, 0.f, 0.f, 0.f);
    int e = lo;
    for (; e + 8 <= hi; e += 8) {
        int ss[8];
        #pragma unroll
        for (int q = 0; q < 8; q++) ss[q] = srcS[e + q];
        uint2 u[8];
        #pragma unroll
        for (int q = 0; q < 8; q++) u[q] = h2[(size_t)ss[q] * 32 + lane];
        float aq[8];
        #pragma unroll
        for (int q = 0; q < 8; q++) aq[q] = 1.0f / (1.0f + __expf(sd - scores[ss[q]]));
        #pragma unroll
        for (int q = 0; q < 8; q++) {
            float a = aq[q], b = 1.0f - aq[q];
            float2 p = __half22float2(*(__half2*)&u[q].x);
            float2 r = __half22float2(*(__half2*)&u[q].y);
            af.x += p.x*a; af.y += p.y*a; af.z += r.x*a; af.w += r.y*a;
            ab.x += p.x*b; ab.y += p.y*b; ab.z += r.x*b; ab.w += r.y*b;
        }
    }
    for (; e + 4 <= hi; e += 4) {
        int ss[4];
        #pragma unroll
        for (int q = 0; q < 4; q++) ss[q] = srcS[e + q];
        uint2 u[4];
        #pragma unroll
        for (int q = 0; q < 4; q++) u[q] = h2[(size_t)ss[q] * 32 + lane];
        #pragma unroll
        for (int q = 0; q < 4; q++) {
            float a = 1.0f / (1.0f + __expf(sd - scores[ss[q]]));
            float b = 1.0f - a;
            float2 p = __half22float2(*(__half2*)&u[q].x);
            float2 r = __half22float2(*(__half2*)&u[q].y);
            af.x += p.x*a; af.y += p.y*a; af.z += r.x*a; af.w += r.y*a;
            ab.x += p.x*b; ab.y += p.y*b; ab.z += r.x*b; ab.w += r.y*b;
        }
    }
    for (; e < hi; e++) {
        int s = srcS[e];
        float a = 1.0f / (1.0f + __expf(sd - scores[s]));
        float b = 1.0f - a;
        uint2 u = h2[(size_t)s * 32 + lane];
        float2 p = __half22float2(*(__half2*)&u.x);
        float2 r = __half22float2(*(__half2*)&u.y);
        af.x += p.x*a; af.y += p.y*a; af.z += r.x*a; af.w += r.y*a;
        ab.x += p.x*b; ab.y += p.y*b; ab.z += r.x*b; ab.w += r.y*b;
    }
    uint2 of, ob;
    *(__half2*)&of.x = __floats2half2_rn(af.x, af.y);
    *(__half2*)&of.y = __floats2half2_rn(af.z, af.w);
    *(__half2*)&ob.x = __floats2half2_rn(ab.x, ab.y);
    *(__half2*)&ob.y = __floats2half2_rn(ab.z, ab.w);
    aF16[(size_t)node * 32 + lane] = of;
    aB16[(size_t)node * 32 + lane] = ob;
}

// ================= prep kernels =================
__global__ void prep_M_kernel(const float* __restrict__ Wcomb,
                              const float* __restrict__ Wself,
                              const float* __restrict__ Wfwd,
                              const float* __restrict__ Wbwd,
                              float* __restrict__ M)
{
    int b = blockIdx.x;
    int rc = b & 7;
    int m  = (b >> 3) % 3;
    int l  = b / 24;
    const float* src = (m == 0) ? (Wself + l * DIM * DIM)
                   : (m == 1) ? (Wfwd + l * DIM * DIM)
                              : (Wbwd + l * DIM * DIM);
    int j = threadIdx.x;

    __shared__ float wcs[16][DIM];
    #pragma unroll
    for (int i = 0; i < 16; i++) {
        int row = rc * 16 + i;
        wcs[i][j] = Wcomb[l * DIM * 3 * DIM + row * 3 * DIM + m * DIM + j];
    }
    __syncthreads();

    float acc[16];
    #pragma unroll
    for (int i = 0; i < 16; i++) acc[i] = 0.0f;
    for (int k = 0; k < DIM; k++) {
        float w = src[k * DIM + j];
        #pragma unroll
        for (int i = 0; i < 16; i++) acc[i] += wcs[i][k] * w;
    }
    float* dst = M + (l * 3 + m) * DIM * DIM;
    #pragma unroll
    for (int i = 0; i < 16; i++) dst[(rc * 16 + i) * DIM + j] = acc[i];
}

__global__ void prep_b_kernel(const float* __restrict__ Wcomb,
                              const float* __restrict__ bself,
                              const float* __restrict__ bcomb,
                              float* __restrict__ bc)
{
    int l = blockIdx.x;
    int i = threadIdx.x;
    float s = bcomb[l * DIM + i];
    for (int k = 0; k < DIM; k++)
        s += Wcomb[l * DIM * 3 * DIM + i * 3 * DIM + k] * bself[l * DIM + k];
    bc[l * DIM + i] = s;
}

__global__ void prep_Wf16_kernel(const float* __restrict__ Wemb,
                                 const float* __restrict__ M,
                                 __half* __restrict__ Wh)
{
    int idx = blockIdx.x * blockDim.x + threadIdx.x;
    if (idx >= 10 * DIM * DIM) return;
    int mat = idx / (DIM * DIM);
    int rem = idx % (DIM * DIM);
    float w = (mat == 0) ? Wemb[rem] : M[(mat - 1) * DIM * DIM + rem];
    Wh[idx] = __float2half_rn(w);
}

// ================= tensor-core GEMM (single fp16) + fused epilogue =================
#define OFF_BIAS  0
#define OFF_GAMMA 512
#define OFF_BETA  1024
#define OFF_WSC   1536
#define OFF_MU    2048
#define OFF_RS    2560
#define OFF_SC    3072
#define AHI_OFF   4096
#define WHI_OFF   (4096 + 18432)
#define MM_SMEM   (4096 + 66048)
#define BF_STRIDE 144

__global__ void __launch_bounds__(256, 2)
mm_mma_kernel(const float* __restrict__ A0,
              const __half* __restrict__ A1,
              const __half* __restrict__ A2,
              const __half* __restrict__ Whb,
              const float* __restrict__ bias,
              const float* __restrict__ gamma,
              const float* __restrict__ beta,
              const float* __restrict__ wsc,
              const float* __restrict__ bscp,
              float* __restrict__ hOut,
              __half* __restrict__ h16Out,
              float* __restrict__ scoresOut,
              int n, int nsrc, int mode)
{
    extern __shared__ char smem[];
    uint32_t smemU = smem_to_u32(smem);
    int tid = threadIdx.x;
    int lane = tid & 31;
    int warp = tid >> 5;
    int base = blockIdx.x * 128;

    float* bias_s  = (float*)(smem + OFF_BIAS);
    float* gamma_s = (float*)(smem + OFF_GAMMA);
    float* beta_s  = (float*)(smem + OFF_BETA);
    float* wsc_s   = (float*)(smem + OFF_WSC);
    float* mu_s    = (float*)(smem + OFF_MU);
    float* rs_s    = (float*)(smem + OFF_RS);
    float* sc_s    = (float*)(smem + OFF_SC);

    if (tid < 128) {
        bias_s[tid] = bias ? bias[tid] : 0.0f;
        if (mode == 1) { gamma_s[tid] = gamma[tid]; beta_s[tid] = beta[tid]; }
        if (wsc) wsc_s[tid] = wsc[tid];
        sc_s[tid] = 0.0f;
    }

    int mO = (warp >> 2) * 64;
    int nO = (warp & 3) * 32;
    uint32_t aLaneOff = (uint32_t)((lane & 15) * BF_STRIDE + ((lane >> 4) << 4));
    uint32_t bLaneOff = (uint32_t)((lane & 7) * BF_STRIDE + (((lane >> 3) & 1) << 4));

    float acc[4][4][4];
    #pragma unroll
    for (int mt = 0; mt < 4; mt++)
        #pragma unroll
        for (int nt = 0; nt < 4; nt++)
            #pragma unroll
            for (int r = 0; r < 4; r++) acc[mt][nt][r] = 0.0f;

    const int nchunks = nsrc * 2;
    for (int c = 0; c < nchunks; c++) {
        int s = c >> 1;
        int half = c & 1;

        __syncthreads();

        // --- W chunk via cp.async
        {
            const char* WhG = (const char*)(Whb + (size_t)s * DIM * DIM);
            #pragma unroll
            for (int i = 0; i < 4; i++) {
                int idx = tid + i * 256;
                int row = idx >> 3;
                int qq  = idx & 7;
                uint32_t dst = smemU + WHI_OFF + row * BF_STRIDE + qq * 16;
                const char* srcp = WhG + row * 256 + half * 128 + qq * 16;
                CP_ASYNC16(dst, srcp);
            }
        }

        if (s == 0) {
            CP_ASYNC_COMMIT();
            #pragma unroll
            for (int i = 0; i < 8; i++) {
                int idx = tid + i * 256;
                int row = idx >> 4;
                int k4  = idx & 15;
                int gn = base + row;
                float4 v = make_float4(0.f, 0.f, 0.f, 0.f);
                if (gn < n)
                    v = *reinterpret_cast<const float4*>(A0 + (size_t)gn * DIM + half * 64 + k4 * 4);
                __half2 h01 = __floats2half2_rn(v.x, v.y);
                __half2 h23 = __floats2half2_rn(v.z, v.w);
                unsigned off = row * BF_STRIDE + k4 * 8;
                *(__half2*)(smem + AHI_OFF + off)     = h01;
                *(__half2*)(smem + AHI_OFF + off + 4) = h23;
            }
        } else {
            const char* AG = (const char*)((s == 1) ? A1 : A2);
            #pragma unroll
            for (int i = 0; i < 4; i++) {
                int idx = tid + i * 256;
                int row = idx >> 3;
                int qq  = idx & 7;
                int gn = base + row;
                uint32_t dstOff = AHI_OFF + row * BF_STRIDE + qq * 16;
                if (gn < n) {
                    const char* srcp = AG + (size_t)gn * 256 + half * 128 + qq * 16;
                    CP_ASYNC16(smemU + dstOff, srcp);
                } else {
                    *reinterpret_cast<uint4*>(smem + dstOff) = make_uint4(0u, 0u, 0u, 0u);
                }
            }
            CP_ASYNC_COMMIT();
        }
        CP_ASYNC_WAIT0();
        __syncthreads();

        #pragma unroll
        for (int ks = 0; ks < 4; ks++) {
            uint32_t kb2 = ks * 32;
            uint32_t bw[4][2];
            #pragma unroll
            for (int nt = 0; nt < 4; nt++) {
                uint32_t addr = smemU + WHI_OFF + (nO + nt * 8) * BF_STRIDE + kb2 + bLaneOff;
                LDSM_X2(bw[nt], addr);
            }
            #pragma unroll
            for (int mt = 0; mt < 4; mt++) {
                uint32_t ahi[4];
                uint32_t addr = smemU + AHI_OFF + (mO + mt * 16) * BF_STRIDE + kb2 + aLaneOff;
                LDSM_X4(ahi, addr);
                #pragma unroll
                for (int nt = 0; nt < 4; nt++)
                    MMA16816F16(acc[mt][nt], ahi, bw[nt]);
            }
        }
    }
    __syncthreads();

    // ---------------- epilogue ----------------
    float* acc_sm = (float*)(smem + AHI_OFF);
    #pragma unroll
    for (int mt = 0; mt < 4; mt++)
        #pragma unroll
        for (int nt = 0; nt < 4; nt++) {
            int R = mO + mt * 16 + (lane >> 2);
            int C = nO + nt * 8 + 2 * (lane & 3);
            acc_sm[R * 129 + C]           = acc[mt][nt][0];
            acc_sm[R * 129 + C + 1]       = acc[mt][nt][1];
            acc_sm[(R + 8) * 129 + C]     = acc[mt][nt][2];
            acc_sm[(R + 8) * 129 + C + 1] = acc[mt][nt][3];
        }
    __syncthreads();

    if (mode == 1 && tid < 128) {
        int r = tid;
        float sum = 0.0f, sq = 0.0f;
        #pragma unroll 4
        for (int j = 0; j < 128; j++) {
            float v = acc_sm[r * 129 + j] + bias_s[j];
            sum += v;
            sq  += v * v;
        }
        float mu = sum * (1.0f / 128.0f);
        mu_s[r] = mu;
        rs_s[r] = rsqrtf(fmaxf(sq * (1.0f / 128.0f) - mu * mu, 0.0f) + LN_EPS);
    }
    __syncthreads();

    #pragma unroll 2
    for (int i = 0; i < 64; i++) {
        int idx = i * 256 + tid;
        int r = idx >> 7;
        int j = idx & 127;
        int gn = base + r;
        float v = acc_sm[r * 129 + j] + bias_s[j];
        float rnew;
        if (mode == 1) {
            float dn = (v - mu_s[r]) * rs_s[r];
            float idv = (gn < n) ? hOut[(size_t)gn * DIM + j] : 0.0f;
            rnew = fmaxf(dn * gamma_s[j] + beta_s[j], 0.0f) + idv;
        } else {
            rnew = fmaxf(v, 0.0f);
        }
        if (gn < n) {
            hOut[(size_t)gn * DIM + j] = rnew;
            h16Out[(size_t)gn * DIM + j] = __float2half_rn(rnew);
        }
        if (wsc) {
            float p = rnew * wsc_s[j];
            #pragma unroll
            for (int o = 16; o > 0; o >>= 1) p += __shfl_xor_sync(0xFFFFFFFFu, p, o);
            if (lane == 0) atomicAdd(&sc_s[r], p);
        }
    }
    if (wsc) {
        __syncthreads();
        if (tid < 128 && base + tid < n)
            scoresOut[base + tid] = sc_s[tid] + bscp[0];
    }
}

// ================= pool =================
__device__ __forceinline__ int lb_idx(const void* buf, int n, int val)
{
    int lo = 0, hi = n;
    while (lo < hi) {
        int mid = (lo + hi) >> 1;
        int bv;
        if (g_is64) bv = (int)((const long long*)buf)[mid];
        else        bv = ((const int*)buf)[mid];
        if (bv < val) lo = mid + 1; else hi = mid;
    }
    return lo;
}

__global__ void zero_out_kernel(float* __restrict__ p, int n)
{
    int i = blockIdx.x * blockDim.x + threadIdx.x;
    if (i < n) p[i] = 0.0f;
}

__global__ void pool_kernel(const float* __restrict__ h,
                            const void* __restrict__ batch,
                            float* __restrict__ out)
{
    int g = blockIdx.x;
    int slice = blockIdx.y;
    int j = threadIdx.x;
    __shared__ int s_lo, s_hi;
    if (j == 0) {
        s_lo = lb_idx(batch, N_NODES, g);
        s_hi = lb_idx(batch, N_NODES, g + 1);
    }
    __syncthreads();
    float sum = 0.0f;
    for (int nd = s_lo + slice; nd < s_hi; nd += 8)
        sum += h[(size_t)nd * DIM + j];
    float c = fmaxf((float)(s_hi - s_lo), 1.0f);
    atomicAdd(&out[g * DIM + j], sum / c);
}

// ================= launch =================
extern "C" void kernel_launch(void* const* d_in, const int* in_sizes, int n_in,
                              void* d_out, int out_size)
{
    const float* x      = (const float*)d_in[0];
    const void*  ei     = d_in[1];
    const void*  batch  = d_in[2];
    const float* Wemb   = (const float*)d_in[3];
    const float* bemb   = (const float*)d_in[4];
    const float* Wscore = (const float*)d_in[5];
    const float* bscore = (const float*)d_in[6];
    const float* Wfwd   = (const float*)d_in[7];
    const float* Wbwd   = (const float*)d_in[8];
    const float* Wself  = (const float*)d_in[9];
    const float* bself  = (const float*)d_in[10];
    const float* Wcomb  = (const float*)d_in[11];
    const float* bcomb  = (const float*)d_in[12];
    const float* gamma  = (const float*)d_in[13];
    const float* beta   = (const float*)d_in[14];
    float* out = (float*)d_out;

    float *pH, *pS, *pM, *pBC;
    __half *pWh, *pH16, *pAF16, *pAB16;
    int *pDeg, *pOff, *pCur, *pSrcS, *pBsum;
    cudaGetSymbolAddress((void**)&pH,  g_h);
    cudaGetSymbolAddress((void**)&pH16, g_h16);
    cudaGetSymbolAddress((void**)&pAF16, g_aF16);
    cudaGetSymbolAddress((void**)&pAB16, g_aB16);
    cudaGetSymbolAddress((void**)&pS,  g_scores);
    cudaGetSymbolAddress((void**)&pM,  g_M);
    cudaGetSymbolAddress((void**)&pBC, g_bc);
    cudaGetSymbolAddress((void**)&pWh, g_Wh);
    cudaGetSymbolAddress((void**)&pDeg,  g_deg);
    cudaGetSymbolAddress((void**)&pOff,  g_off);
    cudaGetSymbolAddress((void**)&pCur,  g_cur);
    cudaGetSymbolAddress((void**)&pSrcS, g_srcS);
    cudaGetSymbolAddress((void**)&pBsum, g_bsum);

    cudaFuncSetAttribute(mm_mma_kernel, cudaFuncAttributeMaxDynamicSharedMemorySize, MM_SMEM);

    static cudaStream_t s2 = nullptr;
    static cudaEvent_t e1 = nullptr, e2 = nullptr;
    if (!s2) {
        cudaStreamCreateWithFlags(&s2, cudaStreamNonBlocking);
        cudaEventCreateWithFlags(&e1, cudaEventDisableTiming);
        cudaEventCreateWithFlags(&e2, cudaEventDisableTiming);
    }

    const int tileBlocks = (N_NODES + 127) / 128;
    const int warpBlocks = (N_NODES + 7) / 8;
    const int edgeThBlocks = (N_EDGES + 255) / 256;

    detect_kernel<<<1, 256>>>((const unsigned int*)ei);
    cudaEventRecord(e1, 0);

    // --- fork: CSR chain on s2 ---
    cudaStreamWaitEvent(s2, e1, 0);
    zero_int_kernel<<<(N_NODES + 255) / 256, 256, 0, s2>>>(pDeg, N_NODES);
    count_kernel<<<edgeThBlocks, 256, 0, s2>>>(ei, pDeg);
    scan_local_kernel<<<SCAN_BLOCKS, 256, 0, s2>>>(pDeg, pOff, pBsum);
    scan_bsum_kernel<<<1, 256, 0, s2>>>(pBsum, pOff);
    scan_add_kernel<<<SCAN_BLOCKS, 256, 0, s2>>>(pOff, pBsum, pCur);
    scatter_kernel<<<edgeThBlocks, 256, 0, s2>>>(ei, pCur, pSrcS);
    cudaEventRecord(e2, s2);

    // --- main stream: weight prep + embed GEMM ---
    prep_M_kernel<<<72, 128>>>(Wcomb, Wself, Wfwd, Wbwd, pM);
    prep_b_kernel<<<N_LAYERS, 128>>>(Wcomb, bself, bcomb, pBC);
    prep_Wf16_kernel<<<(10 * DIM * DIM + 255) / 256, 256>>>(Wemb, pM, pWh);

    mm_mma_kernel<<<tileBlocks, 256, MM_SMEM>>>(
        x, nullptr, nullptr, pWh, bemb,
        nullptr, nullptr, Wscore, bscore,
        pH, pH16, pS, N_NODES, 1, 0);

    // --- join: layers need CSR ---
    cudaStreamWaitEvent(0, e2, 0);

    for (int l = 0; l < N_LAYERS; l++) {
        agg_kernel<<<warpBlocks, 256>>>(pOff, pSrcS, pS, pH16,
                                        (uint2*)pAF16, (uint2*)pAB16);
        const float* wsc_next = (l + 1 < N_LAYERS) ? (Wscore + (l + 1) * DIM) : nullptr;
        const float* bsc_next = (l + 1 < N_LAYERS) ? (bscore + (l + 1)) : nullptr;
        mm_mma_kernel<<<tileBlocks, 256, MM_SMEM>>>(
            pH, pAF16, pAB16,
            pWh + (size_t)(1 + l * 3) * DIM * DIM,
            pBC + l * DIM, gamma + l * DIM, beta + l * DIM,
            wsc_next, bsc_next,
            pH, pH16, pS, N_NODES, 3, 1);
    }

    zero_out_kernel<<<(N_GRAPHS * DIM + 255) / 256, 256>>>(out, N_GRAPHS * DIM);
    pool_kernel<<<dim3(N_GRAPHS, 8), DIM>>>(pH, batch, out);
}

// round 17
// speedup vs baseline: 1.1581x; 1.1581x over previous
#include <cuda_runtime.h>
#include <cuda_fp16.h>
#include <math.h>
#include <stdint.h>

#define N_NODES 50000
#define N_EDGES 625000
#define DIM 128
#define N_LAYERS 3
#define N_GRAPHS 64
#define LN_EPS 1e-5f

__device__ __forceinline__ uint32_t smem_to_u32(const void* smem_ptr) {
    uint32_t addr;
    asm("{ .reg .u64 tmp; cvta.to.shared.u64 tmp, %1; cvt.u32.u64 %0, tmp; }"
        : "=r"(addr) : "l"(smem_ptr));
    return addr;
}

// ---- warp MMA primitives (baseline PTX, sm_80+) ----
#define LDSM_X4(r, addr) \
    asm volatile("ldmatrix.sync.aligned.m8n8.x4.shared.b16 {%0,%1,%2,%3}, [%4];" \
        : "=r"((r)[0]), "=r"((r)[1]), "=r"((r)[2]), "=r"((r)[3]) : "r"(addr))
#define LDSM_X2(r, addr) \
    asm volatile("ldmatrix.sync.aligned.m8n8.x2.shared.b16 {%0,%1}, [%2];" \
        : "=r"((r)[0]), "=r"((r)[1]) : "r"(addr))
#define MMA16816F16(d, a, b) \
    asm volatile("mma.sync.aligned.m16n8k16.row.col.f32.f16.f16.f32 " \
        "{%0,%1,%2,%3}, {%4,%5,%6,%7}, {%8,%9}, {%0,%1,%2,%3};" \
        : "+f"((d)[0]), "+f"((d)[1]), "+f"((d)[2]), "+f"((d)[3]) \
        : "r"((a)[0]), "r"((a)[1]), "r"((a)[2]), "r"((a)[3]), \
          "r"((b)[0]), "r"((b)[1]))
#define CP_ASYNC16(dst, src) \
    asm volatile("cp.async.ca.shared.global [%0], [%1], 16;" \
        :: "r"(dst), "l"(src) : "memory")
#define CP_ASYNC_COMMIT() asm volatile("cp.async.commit_group;" ::: "memory")
#define CP_ASYNC_WAIT0()  asm volatile("cp.async.wait_group 0;" ::: "memory")
#define CP_ASYNC_WAIT1()  asm volatile("cp.async.wait_group 1;" ::: "memory")

// ================= device scratch =================
__device__ float g_h[N_NODES * DIM];
__device__ __half g_h16[N_NODES * DIM];
__device__ __half g_aF16[N_NODES * DIM];
__device__ __half g_aB16[N_NODES * DIM];
__device__ float g_scores[N_NODES];
__device__ float g_M[9 * DIM * DIM];
__device__ float g_bc[N_LAYERS * DIM];
__device__ __half g_Wh[10 * DIM * DIM];
__device__ int g_is64;
// CSR
__device__ int g_deg[N_NODES];
__device__ int g_off[N_NODES + 1];
__device__ int g_cur[N_NODES];
__device__ int g_srcS[N_EDGES];
__device__ int g_bsum[256];

#define SCAN_BLOCKS ((N_NODES + 255) / 256)

// ================= dtype detection =================
__global__ void detect_kernel(const unsigned int* __restrict__ p)
{
    __shared__ int nz;
    if (threadIdx.x == 0) nz = 0;
    __syncthreads();
    for (int i = threadIdx.x; i < 4096; i += blockDim.x)
        if (p[2 * i + 1] != 0u) atomicOr(&nz, 1);
    __syncthreads();
    if (threadIdx.x == 0) g_is64 = nz ? 0 : 1;
}

__device__ __forceinline__ int load_idx(const void* buf, long long i)
{
    int v;
    if (g_is64) v = (int)((const long long*)buf)[i];
    else        v = ((const int*)buf)[i];
    v = v < 0 ? 0 : (v >= N_NODES ? N_NODES - 1 : v);
    return v;
}

// ================= CSR build =================
__global__ void zero_int_kernel(int* __restrict__ p, int n)
{
    int i = blockIdx.x * blockDim.x + threadIdx.x;
    if (i < n) p[i] = 0;
}

__global__ void count_kernel(const void* __restrict__ ei, int* __restrict__ deg)
{
    int e = blockIdx.x * blockDim.x + threadIdx.x;
    if (e >= N_EDGES) return;
    int d = load_idx(ei, (long long)N_EDGES + e);
    atomicAdd(&deg[d], 1);
}

__global__ void scan_local_kernel(const int* __restrict__ deg,
                                  int* __restrict__ off,
                                  int* __restrict__ bsum)
{
    __shared__ int tmp[256];
    int t = threadIdx.x;
    int node = blockIdx.x * 256 + t;
    int v = (node < N_NODES) ? deg[node] : 0;
    tmp[t] = v;
    __syncthreads();
    #pragma unroll
    for (int o = 1; o < 256; o <<= 1) {
        int u = (t >= o) ? tmp[t - o] : 0;
        __syncthreads();
        tmp[t] += u;
        __syncthreads();
    }
    if (node < N_NODES) off[node] = tmp[t] - v;
    if (t == 255) bsum[blockIdx.x] = tmp[255];
}

__global__ void scan_bsum_kernel(int* __restrict__ bsum, int* __restrict__ off)
{
    __shared__ int tmp[256];
    int t = threadIdx.x;
    int v = (t < SCAN_BLOCKS) ? bsum[t] : 0;
    tmp[t] = v;
    __syncthreads();
    #pragma unroll
    for (int o = 1; o < 256; o <<= 1) {
        int u = (t >= o) ? tmp[t - o] : 0;
        __syncthreads();
        tmp[t] += u;
        __syncthreads();
    }
    if (t < SCAN_BLOCKS) bsum[t] = tmp[t] - v;
    if (t == 255) off[N_NODES] = tmp[255];
}

__global__ void scan_add_kernel(int* __restrict__ off,
                                const int* __restrict__ bsum,
                                int* __restrict__ cur)
{
    int node = blockIdx.x * 256 + threadIdx.x;
    if (node >= N_NODES) return;
    int o = off[node] + bsum[blockIdx.x];
    off[node] = o;
    cur[node] = o;
}

__global__ void scatter_kernel(const void* __restrict__ ei,
                               int* __restrict__ cur,
                               int* __restrict__ srcS)
{
    int e = blockIdx.x * blockDim.x + threadIdx.x;
    if (e >= N_EDGES) return;
    int s = load_idx(ei, e);
    int d = load_idx(ei, (long long)N_EDGES + e);
    int pos = atomicAdd(&cur[d], 1);
    srcS[pos] = s;
}

// ================= aggregation (warp per dst node, 4-wide, fp16 in+out) ========
__global__ void agg_kernel(const int* __restrict__ off,
                           const int* __restrict__ srcS,
                           const float* __restrict__ scores,
                           const __half* __restrict__ h16,
                           uint2* __restrict__ aF16,
                           uint2* __restrict__ aB16)
{
    int node = (blockIdx.x * blockDim.x + threadIdx.x) >> 5;
    int lane = threadIdx.x & 31;
    if (node >= N_NODES) return;
    int lo = off[node], hi = off[node + 1];
    float sd = scores[node];
    const uint2* h2 = reinterpret_cast<const uint2*>(h16);
    float4 af = make_float4(0.f, 0.f, 0.f, 0.f);
    float4 ab = make_float4(0.f, 0.f, 0.f, 0.f);
    int e = lo;
    for (; e + 4 <= hi; e += 4) {
        int s0 = srcS[e + 0], s1 = srcS[e + 1], s2 = srcS[e + 2], s3 = srcS[e + 3];
        float c0 = scores[s0], c1 = scores[s1], c2 = scores[s2], c3 = scores[s3];
        uint2 u0 = h2[(size_t)s0 * 32 + lane];
        uint2 u1 = h2[(size_t)s1 * 32 + lane];
        uint2 u2 = h2[(size_t)s2 * 32 + lane];
        uint2 u3 = h2[(size_t)s3 * 32 + lane];
        float a0 = 1.0f / (1.0f + __expf(sd - c0));
        float a1 = 1.0f / (1.0f + __expf(sd - c1));
        float a2 = 1.0f / (1.0f + __expf(sd - c2));
        float a3 = 1.0f / (1.0f + __expf(sd - c3));
        float b0 = 1.f-a0, b1 = 1.f-a1, b2 = 1.f-a2, b3 = 1.f-a3;
        float2 p, q;
        p = __half22float2(*(__half2*)&u0.x); q = __half22float2(*(__half2*)&u0.y);
        af.x += p.x*a0; af.y += p.y*a0; af.z += q.x*a0; af.w += q.y*a0;
        ab.x += p.x*b0; ab.y += p.y*b0; ab.z += q.x*b0; ab.w += q.y*b0;
        p = __half22float2(*(__half2*)&u1.x); q = __half22float2(*(__half2*)&u1.y);
        af.x += p.x*a1; af.y += p.y*a1; af.z += q.x*a1; af.w += q.y*a1;
        ab.x += p.x*b1; ab.y += p.y*b1; ab.z += q.x*b1; ab.w += q.y*b1;
        p = __half22float2(*(__half2*)&u2.x); q = __half22float2(*(__half2*)&u2.y);
        af.x += p.x*a2; af.y += p.y*a2; af.z += q.x*a2; af.w += q.y*a2;
        ab.x += p.x*b2; ab.y += p.y*b2; ab.z += q.x*b2; ab.w += q.y*b2;
        p = __half22float2(*(__half2*)&u3.x); q = __half22float2(*(__half2*)&u3.y);
        af.x += p.x*a3; af.y += p.y*a3; af.z += q.x*a3; af.w += q.y*a3;
        ab.x += p.x*b3; ab.y += p.y*b3; ab.z += q.x*b3; ab.w += q.y*b3;
    }
    for (; e < hi; e++) {
        int s = srcS[e];
        float a = 1.0f / (1.0f + __expf(sd - scores[s]));
        float b = 1.0f - a;
        uint2 u = h2[(size_t)s * 32 + lane];
        float2 p = __half22float2(*(__half2*)&u.x);
        float2 q = __half22float2(*(__half2*)&u.y);
        af.x += p.x*a; af.y += p.y*a; af.z += q.x*a; af.w += q.y*a;
        ab.x += p.x*b; ab.y += p.y*b; ab.z += q.x*b; ab.w += q.y*b;
    }
    uint2 of, ob;
    *(__half2*)&of.x = __floats2half2_rn(af.x, af.y);
    *(__half2*)&of.y = __floats2half2_rn(af.z, af.w);
    *(__half2*)&ob.x = __floats2half2_rn(ab.x, ab.y);
    *(__half2*)&ob.y = __floats2half2_rn(ab.z, ab.w);
    aF16[(size_t)node * 32 + lane] = of;
    aB16[(size_t)node * 32 + lane] = ob;
}

// ================= prep kernels =================
__global__ void prep_M_kernel(const float* __restrict__ Wcomb,
                              const float* __restrict__ Wself,
                              const float* __restrict__ Wfwd,
                              const float* __restrict__ Wbwd,
                              float* __restrict__ M)
{
    int b = blockIdx.x;
    int rc = b & 7;
    int m  = (b >> 3) % 3;
    int l  = b / 24;
    const float* src = (m == 0) ? (Wself + l * DIM * DIM)
                   : (m == 1) ? (Wfwd + l * DIM * DIM)
                              : (Wbwd + l * DIM * DIM);
    int j = threadIdx.x;

    __shared__ float wcs[16][DIM];
    #pragma unroll
    for (int i = 0; i < 16; i++) {
        int row = rc * 16 + i;
        wcs[i][j] = Wcomb[l * DIM * 3 * DIM + row * 3 * DIM + m * DIM + j];
    }
    __syncthreads();

    float acc[16];
    #pragma unroll
    for (int i = 0; i < 16; i++) acc[i] = 0.0f;
    for (int k = 0; k < DIM; k++) {
        float w = src[k * DIM + j];
        #pragma unroll
        for (int i = 0; i < 16; i++) acc[i] += wcs[i][k] * w;
    }
    float* dst = M + (l * 3 + m) * DIM * DIM;
    #pragma unroll
    for (int i = 0; i < 16; i++) dst[(rc * 16 + i) * DIM + j] = acc[i];
}

__global__ void prep_b_kernel(const float* __restrict__ Wcomb,
                              const float* __restrict__ bself,
                              const float* __restrict__ bcomb,
                              float* __restrict__ bc)
{
    int l = blockIdx.x;
    int i = threadIdx.x;
    float s = bcomb[l * DIM + i];
    for (int k = 0; k < DIM; k++)
        s += Wcomb[l * DIM * 3 * DIM + i * 3 * DIM + k] * bself[l * DIM + k];
    bc[l * DIM + i] = s;
}

__global__ void prep_Wf16_kernel(const float* __restrict__ Wemb,
                                 const float* __restrict__ M,
                                 __half* __restrict__ Wh)
{
    int idx = blockIdx.x * blockDim.x + threadIdx.x;
    if (idx >= 10 * DIM * DIM) return;
    int mat = idx / (DIM * DIM);
    int rem = idx % (DIM * DIM);
    float w = (mat == 0) ? Wemb[rem] : M[(mat - 1) * DIM * DIM + rem];
    Wh[idx] = __float2half_rn(w);
}

// ================= tensor-core GEMM (single fp16, double-buffered) =================
#define OFF_BIAS  0
#define OFF_GAMMA 512
#define OFF_BETA  1024
#define OFF_WSC   1536
#define OFF_MU    2048
#define OFF_RS    2560
#define OFF_SC    3072
#define A_OFF(b)  (4096 + (b) * 18432)
#define W_OFF(b)  (4096 + 36864 + (b) * 18432)
#define MM_SMEM   (4096 + 73728)
#define BF_STRIDE 144

__global__ void __launch_bounds__(256, 2)
mm_mma_kernel(const float* __restrict__ A0,
              const __half* __restrict__ A1,
              const __half* __restrict__ A2,
              const __half* __restrict__ Whb,
              const float* __restrict__ bias,
              const float* __restrict__ gamma,
              const float* __restrict__ beta,
              const float* __restrict__ wsc,
              const float* __restrict__ bscp,
              float* __restrict__ hOut,
              __half* __restrict__ h16Out,
              float* __restrict__ scoresOut,
              int n, int nsrc, int mode)
{
    extern __shared__ char smem[];
    uint32_t smemU = smem_to_u32(smem);
    int tid = threadIdx.x;
    int lane = tid & 31;
    int warp = tid >> 5;
    int base = blockIdx.x * 128;

    float* bias_s  = (float*)(smem + OFF_BIAS);
    float* gamma_s = (float*)(smem + OFF_GAMMA);
    float* beta_s  = (float*)(smem + OFF_BETA);
    float* wsc_s   = (float*)(smem + OFF_WSC);
    float* mu_s    = (float*)(smem + OFF_MU);
    float* rs_s    = (float*)(smem + OFF_RS);
    float* sc_s    = (float*)(smem + OFF_SC);

    if (tid < 128) {
        bias_s[tid] = bias ? bias[tid] : 0.0f;
        if (mode == 1) { gamma_s[tid] = gamma[tid]; beta_s[tid] = beta[tid]; }
        if (wsc) wsc_s[tid] = wsc[tid];
        sc_s[tid] = 0.0f;
    }

    int mO = (warp >> 2) * 64;
    int nO = (warp & 3) * 32;
    uint32_t aLaneOff = (uint32_t)((lane & 15) * BF_STRIDE + ((lane >> 4) << 4));
    uint32_t bLaneOff = (uint32_t)((lane & 7) * BF_STRIDE + (((lane >> 3) & 1) << 4));

    float acc[4][4][4];
    #pragma unroll
    for (int mt = 0; mt < 4; mt++)
        #pragma unroll
        for (int nt = 0; nt < 4; nt++)
            #pragma unroll
            for (int r = 0; r < 4; r++) acc[mt][nt][r] = 0.0f;

    const int nchunks = nsrc * 2;

    // issue loads for chunk c into buffer bf; commits exactly one cp.async group
    auto issue_load = [&](int c, int bf) {
        int s = c >> 1;
        int half = c & 1;
        // W chunk
        {
            const char* WhG = (const char*)(Whb + (size_t)s * DIM * DIM);
            #pragma unroll
            for (int i = 0; i < 4; i++) {
                int idx = tid + i * 256;
                int row = idx >> 3;
                int qq  = idx & 7;
                uint32_t dst = smemU + W_OFF(bf) + row * BF_STRIDE + qq * 16;
                const char* srcp = WhG + row * 256 + half * 128 + qq * 16;
                CP_ASYNC16(dst, srcp);
            }
        }
        if (s == 0) {
            // convert h chunk synchronously
            #pragma unroll
            for (int i = 0; i < 8; i++) {
                int idx = tid + i * 256;
                int row = idx >> 4;
                int k4  = idx & 15;
                int gn = base + row;
                float4 v = make_float4(0.f, 0.f, 0.f, 0.f);
                if (gn < n)
                    v = *reinterpret_cast<const float4*>(A0 + (size_t)gn * DIM + half * 64 + k4 * 4);
                __half2 h01 = __floats2half2_rn(v.x, v.y);
                __half2 h23 = __floats2half2_rn(v.z, v.w);
                unsigned off = A_OFF(bf) + row * BF_STRIDE + k4 * 8;
                *(__half2*)(smem + off)     = h01;
                *(__half2*)(smem + off + 4) = h23;
            }
        } else {
            const char* AG = (const char*)((s == 1) ? A1 : A2);
            #pragma unroll
            for (int i = 0; i < 4; i++) {
                int idx = tid + i * 256;
                int row = idx >> 3;
                int qq  = idx & 7;
                int gn = base + row;
                uint32_t dstOff = A_OFF(bf) + row * BF_STRIDE + qq * 16;
                if (gn < n) {
                    const char* srcp = AG + (size_t)gn * 256 + half * 128 + qq * 16;
                    CP_ASYNC16(smemU + dstOff, srcp);
                } else {
                    *reinterpret_cast<uint4*>(smem + dstOff) = make_uint4(0u, 0u, 0u, 0u);
                }
            }
        }
        CP_ASYNC_COMMIT();
    };

    issue_load(0, 0);
    for (int c = 0; c < nchunks; c++) {
        int bf = c & 1;
        if (c + 1 < nchunks) {
            issue_load(c + 1, bf ^ 1);
            CP_ASYNC_WAIT1();
        } else {
            CP_ASYNC_WAIT0();
        }
        __syncthreads();

        #pragma unroll
        for (int ks = 0; ks < 4; ks++) {
            uint32_t kb2 = ks * 32;
            uint32_t bw[4][2];
            #pragma unroll
            for (int nt = 0; nt < 4; nt++) {
                uint32_t addr = smemU + W_OFF(bf) + (nO + nt * 8) * BF_STRIDE + kb2 + bLaneOff;
                LDSM_X2(bw[nt], addr);
            }
            #pragma unroll
            for (int mt = 0; mt < 4; mt++) {
                uint32_t ahi[4];
                uint32_t addr = smemU + A_OFF(bf) + (mO + mt * 16) * BF_STRIDE + kb2 + aLaneOff;
                LDSM_X4(ahi, addr);
                #pragma unroll
                for (int nt = 0; nt < 4; nt++)
                    MMA16816F16(acc[mt][nt], ahi, bw[nt]);
            }
        }
        __syncthreads();   // buffer bf free for c+2's issue_load
    }

    // ---------------- epilogue ----------------
    float* acc_sm = (float*)(smem + A_OFF(0));   // 128 x 129 fp32 (66048 B fits in 73728)
    #pragma unroll
    for (int mt = 0; mt < 4; mt++)
        #pragma unroll
        for (int nt = 0; nt < 4; nt++) {
            int R = mO + mt * 16 + (lane >> 2);
            int C = nO + nt * 8 + 2 * (lane & 3);
            acc_sm[R * 129 + C]           = acc[mt][nt][0];
            acc_sm[R * 129 + C + 1]       = acc[mt][nt][1];
            acc_sm[(R + 8) * 129 + C]     = acc[mt][nt][2];
            acc_sm[(R + 8) * 129 + C + 1] = acc[mt][nt][3];
        }
    __syncthreads();

    if (mode == 1 && tid < 128) {
        int r = tid;
        float sum = 0.0f, sq = 0.0f;
        #pragma unroll 4
        for (int j = 0; j < 128; j++) {
            float v = acc_sm[r * 129 + j] + bias_s[j];
            sum += v;
            sq  += v * v;
        }
        float mu = sum * (1.0f / 128.0f);
        mu_s[r] = mu;
        rs_s[r] = rsqrtf(fmaxf(sq * (1.0f / 128.0f) - mu * mu, 0.0f) + LN_EPS);
    }
    __syncthreads();

    #pragma unroll 2
    for (int i = 0; i < 64; i++) {
        int idx = i * 256 + tid;
        int r = idx >> 7;
        int j = idx & 127;
        int gn = base + r;
        float v = acc_sm[r * 129 + j] + bias_s[j];
        float rnew;
        if (mode == 1) {
            float dn = (v - mu_s[r]) * rs_s[r];
            float idv = (gn < n) ? hOut[(size_t)gn * DIM + j] : 0.0f;
            rnew = fmaxf(dn * gamma_s[j] + beta_s[j], 0.0f) + idv;
        } else {
            rnew = fmaxf(v, 0.0f);
        }
        if (gn < n) {
            hOut[(size_t)gn * DIM + j] = rnew;
            h16Out[(size_t)gn * DIM + j] = __float2half_rn(rnew);
        }
        if (wsc) {
            float p = rnew * wsc_s[j];
            #pragma unroll
            for (int o = 16; o > 0; o >>= 1) p += __shfl_xor_sync(0xFFFFFFFFu, p, o);
            if (lane == 0) atomicAdd(&sc_s[r], p);
        }
    }
    if (wsc) {
        __syncthreads();
        if (tid < 128 && base + tid < n)
            scoresOut[base + tid] = sc_s[tid] + bscp[0];
    }
}

// ================= pool =================
__device__ __forceinline__ int lb_idx(const void* buf, int n, int val)
{
    int lo = 0, hi = n;
    while (lo < hi) {
        int mid = (lo + hi) >> 1;
        int bv;
        if (g_is64) bv = (int)((const long long*)buf)[mid];
        else        bv = ((const int*)buf)[mid];
        if (bv < val) lo = mid + 1; else hi = mid;
    }
    return lo;
}

__global__ void zero_out_kernel(float* __restrict__ p, int n)
{
    int i = blockIdx.x * blockDim.x + threadIdx.x;
    if (i < n) p[i] = 0.0f;
}

__global__ void pool_kernel(const float* __restrict__ h,
                            const void* __restrict__ batch,
                            float* __restrict__ out)
{
    int g = blockIdx.x;
    int slice = blockIdx.y;
    int j = threadIdx.x;
    __shared__ int s_lo, s_hi;
    if (j == 0) {
        s_lo = lb_idx(batch, N_NODES, g);
        s_hi = lb_idx(batch, N_NODES, g + 1);
    }
    __syncthreads();
    float sum = 0.0f;
    for (int nd = s_lo + slice; nd < s_hi; nd += 8)
        sum += h[(size_t)nd * DIM + j];
    float c = fmaxf((float)(s_hi - s_lo), 1.0f);
    atomicAdd(&out[g * DIM + j], sum / c);
}

// ================= launch =================
extern "C" void kernel_launch(void* const* d_in, const int* in_sizes, int n_in,
                              void* d_out, int out_size)
{
    const float* x      = (const float*)d_in[0];
    const void*  ei     = d_in[1];
    const void*  batch  = d_in[2];
    const float* Wemb   = (const float*)d_in[3];
    const float* bemb   = (const float*)d_in[4];
    const float* Wscore = (const float*)d_in[5];
    const float* bscore = (const float*)d_in[6];
    const float* Wfwd   = (const float*)d_in[7];
    const float* Wbwd   = (const float*)d_in[8];
    const float* Wself  = (const float*)d_in[9];
    const float* bself  = (const float*)d_in[10];
    const float* Wcomb  = (const float*)d_in[11];
    const float* bcomb  = (const float*)d_in[12];
    const float* gamma  = (const float*)d_in[13];
    const float* beta   = (const float*)d_in[14];
    float* out = (float*)d_out;

    float *pH, *pS, *pM, *pBC;
    __half *pWh, *pH16, *pAF16, *pAB16;
    int *pDeg, *pOff, *pCur, *pSrcS, *pBsum;
    cudaGetSymbolAddress((void**)&pH,  g_h);
    cudaGetSymbolAddress((void**)&pH16, g_h16);
    cudaGetSymbolAddress((void**)&pAF16, g_aF16);
    cudaGetSymbolAddress((void**)&pAB16, g_aB16);
    cudaGetSymbolAddress((void**)&pS,  g_scores);
    cudaGetSymbolAddress((void**)&pM,  g_M);
    cudaGetSymbolAddress((void**)&pBC, g_bc);
    cudaGetSymbolAddress((void**)&pWh, g_Wh);
    cudaGetSymbolAddress((void**)&pDeg,  g_deg);
    cudaGetSymbolAddress((void**)&pOff,  g_off);
    cudaGetSymbolAddress((void**)&pCur,  g_cur);
    cudaGetSymbolAddress((void**)&pSrcS, g_srcS);
    cudaGetSymbolAddress((void**)&pBsum, g_bsum);

    cudaFuncSetAttribute(mm_mma_kernel, cudaFuncAttributeMaxDynamicSharedMemorySize, MM_SMEM);

    static cudaStream_t s2 = nullptr;
    static cudaEvent_t e1 = nullptr, e2 = nullptr;
    if (!s2) {
        cudaStreamCreateWithFlags(&s2, cudaStreamNonBlocking);
        cudaEventCreateWithFlags(&e1, cudaEventDisableTiming);
        cudaEventCreateWithFlags(&e2, cudaEventDisableTiming);
    }

    const int tileBlocks = (N_NODES + 127) / 128;
    const int warpBlocks = (N_NODES + 7) / 8;
    const int edgeThBlocks = (N_EDGES + 255) / 256;

    detect_kernel<<<1, 256>>>((const unsigned int*)ei);
    cudaEventRecord(e1, 0);

    // --- fork: CSR chain on s2 ---
    cudaStreamWaitEvent(s2, e1, 0);
    zero_int_kernel<<<(N_NODES + 255) / 256, 256, 0, s2>>>(pDeg, N_NODES);
    count_kernel<<<edgeThBlocks, 256, 0, s2>>>(ei, pDeg);
    scan_local_kernel<<<SCAN_BLOCKS, 256, 0, s2>>>(pDeg, pOff, pBsum);
    scan_bsum_kernel<<<1, 256, 0, s2>>>(pBsum, pOff);
    scan_add_kernel<<<SCAN_BLOCKS, 256, 0, s2>>>(pOff, pBsum, pCur);
    scatter_kernel<<<edgeThBlocks, 256, 0, s2>>>(ei, pCur, pSrcS);
    cudaEventRecord(e2, s2);

    // --- main stream: weight prep + embed GEMM ---
    prep_M_kernel<<<72, 128>>>(Wcomb, Wself, Wfwd, Wbwd, pM);
    prep_b_kernel<<<N_LAYERS, 128>>>(Wcomb, bself, bcomb, pBC);
    prep_Wf16_kernel<<<(10 * DIM * DIM + 255) / 256, 256>>>(Wemb, pM, pWh);

    mm_mma_kernel<<<tileBlocks, 256, MM_SMEM>>>(
        x, nullptr, nullptr, pWh, bemb,
        nullptr, nullptr, Wscore, bscore,
        pH, pH16, pS, N_NODES, 1, 0);

    // --- join: layers need CSR ---
    cudaStreamWaitEvent(0, e2, 0);

    for (int l = 0; l < N_LAYERS; l++) {
        agg_kernel<<<warpBlocks, 256>>>(pOff, pSrcS, pS, pH16,
                                        (uint2*)pAF16, (uint2*)pAB16);
        const float* wsc_next = (l + 1 < N_LAYERS) ? (Wscore + (l + 1) * DIM) : nullptr;
        const float* bsc_next = (l + 1 < N_LAYERS) ? (bscore + (l + 1)) : nullptr;
        mm_mma_kernel<<<tileBlocks, 256, MM_SMEM>>>(
            pH, pAF16, pAB16,
            pWh + (size_t)(1 + l * 3) * DIM * DIM,
            pBC + l * DIM, gamma + l * DIM, beta + l * DIM,
            wsc_next, bsc_next,
            pH, pH16, pS, N_NODES, 3, 1);
    }

    zero_out_kernel<<<(N_GRAPHS * DIM + 255) / 256, 256>>>(out, N_GRAPHS * DIM);
    pool_kernel<<<dim3(N_GRAPHS, 8), DIM>>>(pH, batch, out);
}